// round 14
// baseline (speedup 1.0000x reference)
#include <cuda_runtime.h>
#include <cuda_fp16.h>

#define NN 50000
#define EE 1250000
#define DD 64
#define LL 3
#define SCAN_B 256
#define NBLK ((NN + SCAN_B - 1) / SCAN_B)   // 196

// ---- scratch (static device allocations; referenced ONLY from device code) ----
__device__ int   g_indeg[NN];     // BSS-zero; re-zeroed by scatter_k each call
__device__ float g_dis[NN];
__device__ int   g_off[NN + 1];
__device__ int   g_bsum[NBLK];
__device__ __align__(16) int   g_rank[EE];
__device__ __align__(16) int2  g_edge[EE];        // {src_row, weight bits}
__device__ __align__(16) __half2 g_ha[NN * 32];   // Hs ping
__device__ __align__(16) __half2 g_hb[NN * 32];   // Hs pong

__device__ __forceinline__ unsigned sa(const void* p) {
    return (unsigned)__cvta_generic_to_shared(p);
}

// ---------------------------------------------------------------------------
__global__ void count_k(const int* __restrict__ col) {
    int i = blockIdx.x * blockDim.x + threadIdx.x;   // i < EE/4
    if (i < EE / 4) {
        int4 c4 = ((const int4*)col)[i];
        int r0 = atomicAdd(&g_indeg[c4.x], 1);
        int r1 = atomicAdd(&g_indeg[c4.y], 1);
        int r2 = atomicAdd(&g_indeg[c4.z], 1);
        int r3 = atomicAdd(&g_indeg[c4.w], 1);
        ((int4*)g_rank)[i] = make_int4(r0, r1, r2, r3);
    }
}

__global__ void scan_a() {
    __shared__ int s[SCAN_B];
    int t = threadIdx.x;
    int i = blockIdx.x * SCAN_B + t;
    s[t] = (i < NN) ? g_indeg[i] : 0;
    __syncthreads();
#pragma unroll
    for (int off = SCAN_B / 2; off > 0; off >>= 1) {
        if (t < off) s[t] += s[t + off];
        __syncthreads();
    }
    if (t == 0) g_bsum[blockIdx.x] = s[0];
}

__global__ void scan_c() {
    __shared__ int s[SCAN_B];
    __shared__ int bpre;
    int t = threadIdx.x;
    int pv = (t < NBLK && t < blockIdx.x) ? g_bsum[t] : 0;
    s[t] = pv;
    __syncthreads();
#pragma unroll
    for (int off = SCAN_B / 2; off > 0; off >>= 1) {
        if (t < off) s[t] += s[t + off];
        __syncthreads();
    }
    if (t == 0) bpre = s[0];
    __syncthreads();

    int i = blockIdx.x * SCAN_B + t;
    int v = (i < NN) ? g_indeg[i] : 0;
    s[t] = v;
    __syncthreads();
    for (int off = 1; off < SCAN_B; off <<= 1) {
        int u = (t >= off) ? s[t - off] : 0;
        __syncthreads();
        s[t] += u;
        __syncthreads();
    }
    if (i < NN) g_off[i] = s[t] - v + bpre;
    if (blockIdx.x == 0 && t == 0) g_off[NN] = EE;
}

__global__ void scatter_k(const int* __restrict__ row,
                          const int* __restrict__ col,
                          const float* __restrict__ w) {
    int i = blockIdx.x * blockDim.x + threadIdx.x;
    if (i < EE / 4) {
        int4   r4 = ((const int4*)row)[i];
        int4   c4 = ((const int4*)col)[i];
        float4 w4 = ((const float4*)w)[i];
        int4   k4 = ((const int4*)g_rank)[i];
        g_edge[g_off[c4.x] + k4.x] = make_int2(r4.x, __float_as_int(w4.x));
        g_edge[g_off[c4.y] + k4.y] = make_int2(r4.y, __float_as_int(w4.y));
        g_edge[g_off[c4.z] + k4.z] = make_int2(r4.z, __float_as_int(w4.z));
        g_edge[g_off[c4.w] + k4.w] = make_int2(r4.w, __float_as_int(w4.w));
    }
    if (i < NN / 4) ((int4*)g_indeg)[i] = make_int4(0, 0, 0, 0);
}

__global__ void __launch_bounds__(256) disseg_k() {
    int node = blockIdx.x * 8 + (threadIdx.x >> 5);   // grid = NN/8 exactly
    int lane = threadIdx.x & 31;
    int s = g_off[node], e = g_off[node + 1];
    float sum = 0.f;
    for (int p = s + lane; p < e; p += 32)
        sum += __int_as_float(g_edge[p].y);
#pragma unroll
    for (int o = 16; o; o >>= 1) sum += __shfl_down_sync(0xffffffffu, sum, o);
    if (lane == 0) g_dis[node] = rsqrtf(sum + 2.0f);
}

// ---------------------------------------------------------------------------
// shared mma core: xs(64x72 fp16) @ ws(64x72 fp16) -> Hs rows (dis-scaled fp16)
__device__ __forceinline__ void mma_and_store(const __half (*xs)[72],
                                              const __half (*ws)[72],
                                              int rbase, int wid, int lane,
                                              __half2* __restrict__ dst) {
    int m0 = (wid & 3) * 16;
    int n0 = (wid >> 2) * 32;
    float c[4][4] = {};
#pragma unroll
    for (int kk = 0; kk < 4; ++kk) {
        unsigned a0, a1, a2, a3;
        {
            unsigned addr = sa(&xs[m0 + (lane & 15)][kk * 16 + (lane >> 4) * 8]);
            asm volatile("ldmatrix.sync.aligned.m8n8.x4.shared.b16 {%0,%1,%2,%3}, [%4];"
                         : "=r"(a0), "=r"(a1), "=r"(a2), "=r"(a3) : "r"(addr));
        }
        unsigned b[8];
#pragma unroll
        for (int h = 0; h < 2; ++h) {
            int nb = n0 + h * 16;
            unsigned addr = sa(&ws[kk * 16 + (lane & 7) + ((lane >> 3) & 1) * 8]
                                 [nb + (lane >> 4) * 8]);
            asm volatile("ldmatrix.sync.aligned.m8n8.x4.trans.shared.b16 {%0,%1,%2,%3}, [%4];"
                         : "=r"(b[h * 4]), "=r"(b[h * 4 + 1]), "=r"(b[h * 4 + 2]), "=r"(b[h * 4 + 3])
                         : "r"(addr));
        }
#pragma unroll
        for (int nt = 0; nt < 4; ++nt) {
            asm volatile(
                "mma.sync.aligned.m16n8k16.row.col.f32.f16.f16.f32 "
                "{%0,%1,%2,%3}, {%4,%5,%6,%7}, {%8,%9}, {%0,%1,%2,%3};"
                : "+f"(c[nt][0]), "+f"(c[nt][1]), "+f"(c[nt][2]), "+f"(c[nt][3])
                : "r"(a0), "r"(a1), "r"(a2), "r"(a3),
                  "r"(b[nt * 2]), "r"(b[nt * 2 + 1]));
        }
    }
    int rA = rbase + m0 + (lane >> 2);
    int rB = rA + 8;
    float dA = (rA < NN) ? g_dis[rA] : 0.f;
    float dB = (rB < NN) ? g_dis[rB] : 0.f;
#pragma unroll
    for (int nt = 0; nt < 4; ++nt) {
        int ch2 = ((n0 + nt * 8) >> 1) + (lane & 3);
        if (rA < NN) dst[rA * 32 + ch2] = __floats2half2_rn(c[nt][0] * dA, c[nt][1] * dA);
        if (rB < NN) dst[rB * 32 + ch2] = __floats2half2_rn(c[nt][2] * dB, c[nt][3] * dB);
    }
}

__device__ __forceinline__ void stage_w(const float* __restrict__ W,
                                        __half (*ws)[72], int tid) {
    const float4* W4 = (const float4*)W;
#pragma unroll
    for (int i = 0; i < 4; ++i) {
        int idx4 = tid + i * 256;
        int r = idx4 >> 4, q = idx4 & 15;
        float4 v = W4[idx4];
        *(__half2*)&ws[r][q * 4]     = __floats2half2_rn(v.x, v.y);
        *(__half2*)&ws[r][q * 4 + 2] = __floats2half2_rn(v.z, v.w);
    }
}

// layer 0: HA = dis * (x @ W0), fp32 input
__global__ void __launch_bounds__(256) gemm0_k(const float* __restrict__ xin,
                                               const float* __restrict__ W) {
    __shared__ __half xs[64][72];
    __shared__ __half ws[64][72];
    int tid = threadIdx.x;
    int rbase = blockIdx.x * 64;
    stage_w(W, ws, tid);
    const float4* X4 = (const float4*)xin;
#pragma unroll
    for (int i = 0; i < 4; ++i) {
        int idx4 = tid + i * 256;
        int r = idx4 >> 4, q = idx4 & 15;
        int gr = rbase + r;
        float4 v = (gr < NN) ? X4[gr * 16 + q] : make_float4(0.f, 0.f, 0.f, 0.f);
        *(__half2*)&xs[r][q * 4]     = __floats2half2_rn(v.x, v.y);
        *(__half2*)&xs[r][q * 4 + 2] = __floats2half2_rn(v.z, v.w);
    }
    __syncthreads();
    mma_and_store(xs, ws, rbase, tid >> 5, tid & 31, g_ha);
}

// ---------------------------------------------------------------------------
// warp gather-aggregate of one node from src Hs buffer -> (o0,o1) per lane
// (noinline-friendly small body; called in a NON-unrolled loop to keep code small)
__device__ void gather_node(const __half2* __restrict__ H2,
                            const float* __restrict__ bias,
                            int node, int lane,
                            float& o0, float& o1) {
    float2 hv = __half22float2(H2[node * 32 + lane]);
    float ax = 2.f * hv.x, ay = 2.f * hv.y;
    int p = g_off[node], e = g_off[node + 1];
    for (; p + 3 < e; p += 4) {
        int2 e1 = g_edge[p];
        int2 e2 = g_edge[p + 1];
        int2 e3 = g_edge[p + 2];
        int2 e4 = g_edge[p + 3];
        float2 a = __half22float2(H2[e1.x * 32 + lane]);
        float2 b = __half22float2(H2[e2.x * 32 + lane]);
        float2 c = __half22float2(H2[e3.x * 32 + lane]);
        float2 d = __half22float2(H2[e4.x * 32 + lane]);
        float n1 = __int_as_float(e1.y), n2 = __int_as_float(e2.y);
        float n3 = __int_as_float(e3.y), n4 = __int_as_float(e4.y);
        ax += a.x * n1 + b.x * n2 + c.x * n3 + d.x * n4;
        ay += a.y * n1 + b.y * n2 + c.y * n3 + d.y * n4;
    }
    for (; p < e; ++p) {
        int2 e1 = g_edge[p];
        float n1 = __int_as_float(e1.y);
        float2 a = __half22float2(H2[e1.x * 32 + lane]);
        ax += a.x * n1;
        ay += a.y * n1;
    }
    float dc = g_dis[node];
    o0 = fmaxf(ax * dc + bias[lane * 2    ], 0.f);
    o1 = fmaxf(ay * dc + bias[lane * 2 + 1], 0.f);
}

// fused: y = relu(agg(src) + b); dst = dis * (y @ W).  srcsel 0: HA->HB, 1: HB->HA
__global__ void __launch_bounds__(256) fused_k(const float* __restrict__ bias,
                                               const float* __restrict__ W,
                                               int srcsel) {
    __shared__ __half xs[64][72];
    __shared__ __half ws[64][72];
    int tid = threadIdx.x;
    int wid = tid >> 5, lane = tid & 31;
    int rbase = blockIdx.x * 64;
    stage_w(W, ws, tid);

    const __half2* src = srcsel ? g_hb : g_ha;
    __half2* dst       = srcsel ? g_ha : g_hb;

#pragma unroll 1
    for (int j = 0; j < 8; ++j) {
        int node = rbase + wid * 8 + j;
        __half2 y = __floats2half2_rn(0.f, 0.f);
        if (node < NN) {
            float o0, o1;
            gather_node(src, bias, node, lane, o0, o1);
            y = __floats2half2_rn(o0, o1);
        }
        *(__half2*)&xs[wid * 8 + j][lane * 2] = y;
    }
    __syncthreads();
    mma_and_store(xs, ws, rbase, wid, lane, dst);
}

// final: y = relu(agg(HA) + b2); out = y . Wf + bf
__global__ void __launch_bounds__(256) final_k(const float* __restrict__ bias,
                                               const float* __restrict__ Wf,
                                               const float* __restrict__ bf,
                                               float* __restrict__ out) {
    int node = blockIdx.x * 8 + (threadIdx.x >> 5);   // grid = NN/8 exactly
    int lane = threadIdx.x & 31;
    float o0, o1;
    gather_node(g_ha, bias, node, lane, o0, o1);
    float a = o0 * Wf[lane * 2] + o1 * Wf[lane * 2 + 1];
#pragma unroll
    for (int o = 16; o; o >>= 1) a += __shfl_down_sync(0xffffffffu, a, o);
    if (lane == 0) out[node] = a + bf[0];
}

// ---------------------------------------------------------------------------
extern "C" void kernel_launch(void* const* d_in, const int* in_sizes, int n_in,
                              void* d_out, int out_size) {
    const float* x  = (const float*)d_in[0];
    const int*   ei = (const int*)d_in[1];      // [2, E] (int32 on device)
    const float* ew = (const float*)d_in[2];
    const float* Ws = (const float*)d_in[3];    // [L, 64, 64]
    const float* bs = (const float*)d_in[4];    // [L, 64]
    const float* Wf = (const float*)d_in[5];    // [64, 1]
    const float* bf = (const float*)d_in[6];    // [1]
    float*       out = (float*)d_out;
    // d_in[7] = prob (unused, dropout p=0)

    const int* erow = ei;        // sources (x_j)
    const int* ecol = ei + EE;   // targets (aggregation)

    const int TB = 256;
    const int E4 = EE / 4;
    // CSR build (once, reused by all layers)
    count_k  <<<(E4 + TB - 1) / TB, TB>>>(ecol);
    scan_a   <<<NBLK, SCAN_B>>>();
    scan_c   <<<NBLK, SCAN_B>>>();
    scatter_k<<<(E4 + TB - 1) / TB, TB>>>(erow, ecol, ew);
    disseg_k <<<NN / 8, 256>>>();

    // Hs0 = dis*(x@W0) -> HA
    gemm0_k<<<(NN + 63) / 64, 256>>>(x, Ws + 0 * DD * DD);
    // layer 1: HA -> HB  (agg+relu with b0, gemm W1)
    fused_k<<<(NN + 63) / 64, 256>>>(bs + 0 * DD, Ws + 1 * DD * DD, 0);
    // layer 2: HB -> HA  (agg+relu with b1, gemm W2)
    fused_k<<<(NN + 63) / 64, 256>>>(bs + 1 * DD, Ws + 2 * DD * DD, 1);
    // layer 3 agg + final projection: HA -> out (b2)
    final_k<<<NN / 8, 256>>>(bs + 2 * DD, Wf, bf, out);
}

// round 15
// speedup vs baseline: 1.0944x; 1.0944x over previous
#include <cuda_runtime.h>
#include <cuda_fp16.h>

#define NN 50000
#define EE 1250000
#define DD 64
#define LL 3
#define SCAN_B 256
#define NBLK ((NN + SCAN_B - 1) / SCAN_B)   // 196

// ---- scratch (static device allocations; referenced ONLY from device code) ----
__device__ int   g_indeg[NN];     // BSS-zero; re-zeroed by scatter_k each call
__device__ float g_dis[NN];
__device__ int   g_off[NN + 1];
__device__ int   g_bsum[NBLK];
__device__ __align__(16) int      g_rank[EE];
__device__ __align__(16) unsigned g_edge[EE];     // {src_row:16 | w_fp16:16}
__device__ __align__(16) __half2 g_h2 [NN * 32];  // Hs = dis[r]*H[r]  (fp16)
__device__ __align__(16) __half2 g_xh1[NN * 32];  // activations fp16
__device__ __align__(16) __half2 g_xh2[NN * 32];

__device__ __forceinline__ unsigned sa(const void* p) {
    return (unsigned)__cvta_generic_to_shared(p);
}

__device__ __forceinline__ unsigned pack_edge(int r, float w) {
    return ((unsigned)r << 16) | (unsigned)__half_as_ushort(__float2half_rn(w));
}

// ---------------------------------------------------------------------------
// 1) count in-degree; atomic return value IS the edge's segment rank.
__global__ void count_k(const int* __restrict__ col) {
    int i = blockIdx.x * blockDim.x + threadIdx.x;   // i < EE/4
    if (i < EE / 4) {
        int4 c4 = ((const int4*)col)[i];
        int r0 = atomicAdd(&g_indeg[c4.x], 1);
        int r1 = atomicAdd(&g_indeg[c4.y], 1);
        int r2 = atomicAdd(&g_indeg[c4.z], 1);
        int r3 = atomicAdd(&g_indeg[c4.w], 1);
        ((int4*)g_rank)[i] = make_int4(r0, r1, r2, r3);
    }
}

__global__ void scan_a() {
    __shared__ int s[SCAN_B];
    int t = threadIdx.x;
    int i = blockIdx.x * SCAN_B + t;
    s[t] = (i < NN) ? g_indeg[i] : 0;
    __syncthreads();
#pragma unroll
    for (int off = SCAN_B / 2; off > 0; off >>= 1) {
        if (t < off) s[t] += s[t + off];
        __syncthreads();
    }
    if (t == 0) g_bsum[blockIdx.x] = s[0];
}

__global__ void scan_c() {
    __shared__ int s[SCAN_B];
    __shared__ int bpre;
    int t = threadIdx.x;
    int pv = (t < NBLK && t < blockIdx.x) ? g_bsum[t] : 0;
    s[t] = pv;
    __syncthreads();
#pragma unroll
    for (int off = SCAN_B / 2; off > 0; off >>= 1) {
        if (t < off) s[t] += s[t + off];
        __syncthreads();
    }
    if (t == 0) bpre = s[0];
    __syncthreads();

    int i = blockIdx.x * SCAN_B + t;
    int v = (i < NN) ? g_indeg[i] : 0;
    s[t] = v;
    __syncthreads();
    for (int off = 1; off < SCAN_B; off <<= 1) {
        int u = (t >= off) ? s[t - off] : 0;
        __syncthreads();
        s[t] += u;
        __syncthreads();
    }
    if (i < NN) g_off[i] = s[t] - v + bpre;
    if (blockIdx.x == 0 && t == 0) g_off[NN] = EE;
}

// 3) atomic-free scatter of packed edges; re-zero indeg for next replay.
__global__ void scatter_k(const int* __restrict__ row,
                          const int* __restrict__ col,
                          const float* __restrict__ w) {
    int i = blockIdx.x * blockDim.x + threadIdx.x;
    if (i < EE / 4) {
        int4   r4 = ((const int4*)row)[i];
        int4   c4 = ((const int4*)col)[i];
        float4 w4 = ((const float4*)w)[i];
        int4   k4 = ((const int4*)g_rank)[i];
        g_edge[g_off[c4.x] + k4.x] = pack_edge(r4.x, w4.x);
        g_edge[g_off[c4.y] + k4.y] = pack_edge(r4.y, w4.y);
        g_edge[g_off[c4.z] + k4.z] = pack_edge(r4.z, w4.z);
        g_edge[g_off[c4.w] + k4.w] = pack_edge(r4.w, w4.w);
    }
    if (i < NN / 4) ((int4*)g_indeg)[i] = make_int4(0, 0, 0, 0);
}

// 4) weighted degree via coalesced segmented sum; dis = rsqrt(deg + 2)
__global__ void __launch_bounds__(256) disseg_k() {
    int node = blockIdx.x * 8 + (threadIdx.x >> 5);   // grid = NN/8 exactly
    int lane = threadIdx.x & 31;
    int s = g_off[node], e = g_off[node + 1];
    float sum = 0.f;
    for (int p = s + lane; p < e; p += 32)
        sum += __half2float(__ushort_as_half((unsigned short)(g_edge[p] & 0xFFFFu)));
#pragma unroll
    for (int o = 16; o; o >>= 1) sum += __shfl_down_sync(0xffffffffu, sum, o);
    if (lane == 0) g_dis[node] = rsqrtf(sum + 2.0f);
}

// ---------------------------------------------------------------------------
// Hs = dis[row] * (X @ W), fp16 tensor-core GEMM (m16n8k16, fp32 accum).
// CTA: 64x64, K=64. 8 warps: warp_m = wid%4 (16 rows), warp_n = wid/4 (32 cols).
// src: 0 = fp32 xin, 1 = g_xh1, 2 = g_xh2.
__global__ void __launch_bounds__(256) gemm_k(const float* __restrict__ xin,
                                              int src,
                                              const float* __restrict__ W) {
    __shared__ __half xs[64][72];   // X tile  (pad 72: row 144B, 16B-aligned)
    __shared__ __half ws[64][72];   // W[k][n]
    int tid = threadIdx.x;
    int rbase = blockIdx.x * 64;

    // stage W: fp32 -> fp16
    {
        const float4* W4 = (const float4*)W;
#pragma unroll
        for (int i = 0; i < 4; ++i) {
            int idx4 = tid + i * 256;          // 0..1023
            int r = idx4 >> 4, q = idx4 & 15;
            float4 v = W4[idx4];
            *(__half2*)&ws[r][q * 4]     = __floats2half2_rn(v.x, v.y);
            *(__half2*)&ws[r][q * 4 + 2] = __floats2half2_rn(v.z, v.w);
        }
    }

    // stage X tile
    if (src == 0) {
        const float4* X4 = (const float4*)xin;
#pragma unroll
        for (int i = 0; i < 4; ++i) {
            int idx4 = tid + i * 256;
            int r = idx4 >> 4, q = idx4 & 15;
            int gr = rbase + r;
            float4 v = (gr < NN) ? X4[gr * 16 + q] : make_float4(0.f, 0.f, 0.f, 0.f);
            *(__half2*)&xs[r][q * 4]     = __floats2half2_rn(v.x, v.y);
            *(__half2*)&xs[r][q * 4 + 2] = __floats2half2_rn(v.z, v.w);
        }
    } else {
        const uint4* Xh = (const uint4*)((src == 1) ? g_xh1 : g_xh2); // 8 uint4/row
#pragma unroll
        for (int i = 0; i < 2; ++i) {
            int idx = tid + i * 256;           // 0..511
            int r = idx >> 3, q = idx & 7;
            int gr = rbase + r;
            uint4 v = (gr < NN) ? Xh[gr * 8 + q] : make_uint4(0u, 0u, 0u, 0u);
            *(uint4*)&xs[r][q * 8] = v;
        }
    }
    __syncthreads();

    int wid  = tid >> 5, lane = tid & 31;
    int m0 = (wid & 3) * 16;          // warp row base
    int n0 = (wid >> 2) * 32;         // warp col base

    float c[4][4] = {};
#pragma unroll
    for (int kk = 0; kk < 4; ++kk) {
        unsigned a0, a1, a2, a3;
        {
            unsigned addr = sa(&xs[m0 + (lane & 15)][kk * 16 + (lane >> 4) * 8]);
            asm volatile("ldmatrix.sync.aligned.m8n8.x4.shared.b16 {%0,%1,%2,%3}, [%4];"
                         : "=r"(a0), "=r"(a1), "=r"(a2), "=r"(a3) : "r"(addr));
        }
        unsigned b[8];
#pragma unroll
        for (int h = 0; h < 2; ++h) {
            int nb = n0 + h * 16;
            unsigned addr = sa(&ws[kk * 16 + (lane & 7) + ((lane >> 3) & 1) * 8]
                                 [nb + (lane >> 4) * 8]);
            asm volatile("ldmatrix.sync.aligned.m8n8.x4.trans.shared.b16 {%0,%1,%2,%3}, [%4];"
                         : "=r"(b[h * 4]), "=r"(b[h * 4 + 1]), "=r"(b[h * 4 + 2]), "=r"(b[h * 4 + 3])
                         : "r"(addr));
        }
#pragma unroll
        for (int nt = 0; nt < 4; ++nt) {
            asm volatile(
                "mma.sync.aligned.m16n8k16.row.col.f32.f16.f16.f32 "
                "{%0,%1,%2,%3}, {%4,%5,%6,%7}, {%8,%9}, {%0,%1,%2,%3};"
                : "+f"(c[nt][0]), "+f"(c[nt][1]), "+f"(c[nt][2]), "+f"(c[nt][3])
                : "r"(a0), "r"(a1), "r"(a2), "r"(a3),
                  "r"(b[nt * 2]), "r"(b[nt * 2 + 1]));
        }
    }

    // epilogue: Hs = dis[row] * acc, fp16.
    int rA = rbase + m0 + (lane >> 2);
    int rB = rA + 8;
    float dA = (rA < NN) ? g_dis[rA] : 0.f;
    float dB = (rB < NN) ? g_dis[rB] : 0.f;
#pragma unroll
    for (int nt = 0; nt < 4; ++nt) {
        int ch2 = ((n0 + nt * 8) >> 1) + (lane & 3);
        if (rA < NN) g_h2[rA * 32 + ch2] = __floats2half2_rn(c[nt][0] * dA, c[nt][1] * dA);
        if (rB < NN) g_h2[rB * 32 + ch2] = __floats2half2_rn(c[nt][2] * dB, c[nt][3] * dB);
    }
}

// ---------------------------------------------------------------------------
// gather-aggregate: agg = dis[c] * (sum_e w_e*Hs[r_e] + 2*Hs[c]); relu(+bias).
// mode 0: write fp16 to dst (1=g_xh1, 2=g_xh2). mode 1: fused final projection.
__global__ void __launch_bounds__(256) agg_k(const float* __restrict__ bias,
                                             int dst, int mode,
                                             const float* __restrict__ Wf,
                                             const float* __restrict__ bf,
                                             float* __restrict__ out) {
    int node = blockIdx.x * 8 + (threadIdx.x >> 5);   // grid = NN/8 exactly
    int lane = threadIdx.x & 31;

    const __half2* H2 = g_h2;
    float2 hv = __half22float2(H2[node * 32 + lane]);
    float ax = 2.f * hv.x, ay = 2.f * hv.y;

    int p = g_off[node], e = g_off[node + 1];
    for (; p + 3 < e; p += 4) {
        unsigned e1 = g_edge[p];
        unsigned e2 = g_edge[p + 1];
        unsigned e3 = g_edge[p + 2];
        unsigned e4 = g_edge[p + 3];
        float2 a = __half22float2(H2[(e1 >> 16) * 32 + lane]);
        float2 b = __half22float2(H2[(e2 >> 16) * 32 + lane]);
        float2 c = __half22float2(H2[(e3 >> 16) * 32 + lane]);
        float2 d = __half22float2(H2[(e4 >> 16) * 32 + lane]);
        float n1 = __half2float(__ushort_as_half((unsigned short)(e1 & 0xFFFFu)));
        float n2 = __half2float(__ushort_as_half((unsigned short)(e2 & 0xFFFFu)));
        float n3 = __half2float(__ushort_as_half((unsigned short)(e3 & 0xFFFFu)));
        float n4 = __half2float(__ushort_as_half((unsigned short)(e4 & 0xFFFFu)));
        ax += a.x * n1 + b.x * n2 + c.x * n3 + d.x * n4;
        ay += a.y * n1 + b.y * n2 + c.y * n3 + d.y * n4;
    }
    for (; p < e; ++p) {
        unsigned e1 = g_edge[p];
        float n1 = __half2float(__ushort_as_half((unsigned short)(e1 & 0xFFFFu)));
        float2 a = __half22float2(H2[(e1 >> 16) * 32 + lane]);
        ax += a.x * n1;
        ay += a.y * n1;
    }

    float dc = g_dis[node];
    float o0 = fmaxf(ax * dc + bias[lane * 2    ], 0.f);
    float o1 = fmaxf(ay * dc + bias[lane * 2 + 1], 0.f);

    if (mode == 0) {
        __half2* Y = (dst == 1) ? g_xh1 : g_xh2;
        Y[node * 32 + lane] = __floats2half2_rn(o0, o1);
    } else {
        float a = o0 * Wf[lane * 2] + o1 * Wf[lane * 2 + 1];
#pragma unroll
        for (int o = 16; o; o >>= 1) a += __shfl_down_sync(0xffffffffu, a, o);
        if (lane == 0) out[node] = a + bf[0];
    }
}

// ---------------------------------------------------------------------------
extern "C" void kernel_launch(void* const* d_in, const int* in_sizes, int n_in,
                              void* d_out, int out_size) {
    const float* x  = (const float*)d_in[0];
    const int*   ei = (const int*)d_in[1];      // [2, E] (int32 on device)
    const float* ew = (const float*)d_in[2];
    const float* Ws = (const float*)d_in[3];    // [L, 64, 64]
    const float* bs = (const float*)d_in[4];    // [L, 64]
    const float* Wf = (const float*)d_in[5];    // [64, 1]
    const float* bf = (const float*)d_in[6];    // [1]
    float*       out = (float*)d_out;
    // d_in[7] = prob (unused, dropout p=0)

    const int* erow = ei;        // sources (x_j)
    const int* ecol = ei + EE;   // targets (aggregation)

    const int TB = 256;
    const int E4 = EE / 4;
    // CSR build (once, reused by all layers)
    count_k  <<<(E4 + TB - 1) / TB, TB>>>(ecol);
    scan_a   <<<NBLK, SCAN_B>>>();
    scan_c   <<<NBLK, SCAN_B>>>();
    scatter_k<<<(E4 + TB - 1) / TB, TB>>>(erow, ecol, ew);
    disseg_k <<<NN / 8, 256>>>();

    // layer 0: x -> g_h2 -> g_xh1
    gemm_k<<<(NN + 63) / 64, 256>>>(x, 0, Ws + 0 * DD * DD);
    agg_k <<<NN / 8, 256>>>(bs + 0 * DD, 1, 0, Wf, bf, out);
    // layer 1: g_xh1 -> g_h2 -> g_xh2
    gemm_k<<<(NN + 63) / 64, 256>>>(x, 1, Ws + 1 * DD * DD);
    agg_k <<<NN / 8, 256>>>(bs + 1 * DD, 2, 0, Wf, bf, out);
    // layer 2: g_xh2 -> g_h2 -> out (fused final projection)
    gemm_k<<<(NN + 63) / 64, 256>>>(x, 2, Ws + 2 * DD * DD);
    agg_k <<<NN / 8, 256>>>(bs + 2 * DD, 0, 1, Wf, bf, out);
}